// round 6
// baseline (speedup 1.0000x reference)
#include <cuda_runtime.h>
#include <cuda_bf16.h>
#include <cstdint>

// ---------------------------------------------------------------------------
// GCN: out = relu(Agg(relu(Agg(x@W1)+b1)@W2)+b2) @ Wout + bout
// Agg(h)[i] = dinv[i]^2*h[i] + sum_{e: col[e]=i} dinv[row]*dinv[col]*h[row]
// CSR build once -> gather agg (fused bias+relu). Hidden GEMMs: tf32
// mma.m16n8k8 with conflict-free row-major staging + cvt at fragment load.
// ---------------------------------------------------------------------------

#define NN 100000
#define EE 1600000
#define DIM 128
#define SCAN_B 1024

__device__ float g_bufA[(size_t)NN * DIM];
__device__ float g_bufB[(size_t)NN * DIM];
__device__ int   g_cnt[NN];
__device__ float g_dinv[NN];
__device__ int   g_part[NN];
__device__ int   g_bsum[128];
__device__ int   g_rowptr[NN + 1];
__device__ int   g_cursor[NN];
__device__ int   g_edst[EE];
__device__ float g_ew[EE];

// ---------------------------- CSR build -------------------------------------
__global__ void k_count(const int* __restrict__ col, int* __restrict__ cnt, int e) {
    int i = blockIdx.x * blockDim.x + threadIdx.x;
    if (i < e) atomicAdd(&cnt[col[i]], 1);
}

__global__ void k_scan1(const int* __restrict__ cnt, int* __restrict__ part,
                        int* __restrict__ bsum, int n) {
    __shared__ int sh[SCAN_B];
    int t = threadIdx.x;
    int g = blockIdx.x * SCAN_B + t;
    int v = (g < n) ? cnt[g] : 0;
    sh[t] = v;
    __syncthreads();
    for (int off = 1; off < SCAN_B; off <<= 1) {
        int x = (t >= off) ? sh[t - off] : 0;
        __syncthreads();
        sh[t] += x;
        __syncthreads();
    }
    if (g < n) part[g] = sh[t] - v;
    if (t == SCAN_B - 1) bsum[blockIdx.x] = sh[t];
}

__global__ void k_scan2(int* bsum, int nb) {
    __shared__ int sh[128];
    int t = threadIdx.x;
    int v = (t < nb) ? bsum[t] : 0;
    sh[t] = v;
    __syncthreads();
    for (int off = 1; off < 128; off <<= 1) {
        int x = (t >= off) ? sh[t - off] : 0;
        __syncthreads();
        sh[t] += x;
        __syncthreads();
    }
    if (t < nb) bsum[t] = sh[t] - v;
}

__global__ void k_scan3(const int* __restrict__ part, const int* __restrict__ bsum,
                        int* __restrict__ rowptr, int* __restrict__ cursor, int n, int e) {
    int g = blockIdx.x * blockDim.x + threadIdx.x;
    if (g < n) {
        rowptr[g] = part[g] + bsum[g / SCAN_B];
        cursor[g] = 0;
    }
    if (g == 0) rowptr[n] = e;
}

__global__ void k_dinv(const int* __restrict__ cnt, float* __restrict__ dinv, int n) {
    int i = blockIdx.x * blockDim.x + threadIdx.x;
    if (i < n) dinv[i] = rsqrtf((float)(cnt[i] + 1));
}

__global__ void k_bucket(const int* __restrict__ row, const int* __restrict__ col,
                         const float* __restrict__ dinv, const int* __restrict__ rowptr,
                         int* __restrict__ cursor, int* __restrict__ edst,
                         float* __restrict__ ew, int E) {
    int e = blockIdx.x * blockDim.x + threadIdx.x;
    if (e >= E) return;
    int c = col[e];
    int r = row[e];
    int p = rowptr[c] + atomicAdd(&cursor[c], 1);
    edst[p] = r;
    ew[p] = dinv[r] * dinv[c];
}

// ---------------------------- tf32 helpers -----------------------------------
__device__ __forceinline__ uint32_t f2tf32(float x) {
    uint32_t u;
    asm("cvt.rna.tf32.f32 %0, %1;" : "=r"(u) : "f"(x));
    return u;
}

__device__ __forceinline__ void mma_tf32(float* c, const uint32_t* a, const uint32_t* b) {
    asm volatile(
        "mma.sync.aligned.m16n8k8.row.col.f32.tf32.tf32.f32 "
        "{%0,%1,%2,%3}, {%4,%5,%6,%7}, {%8,%9}, {%0,%1,%2,%3};"
        : "+f"(c[0]), "+f"(c[1]), "+f"(c[2]), "+f"(c[3])
        : "r"(a[0]), "r"(a[1]), "r"(a[2]), "r"(a[3]), "r"(b[0]), "r"(b[1]));
}

// ---------------------------- tf32 GEMM (N=K=128) ----------------------------
// 128x128 tile, 256 threads, 8 warps (4m x 2n), each warp 32x64.
// Asm: X chunk [128 rows][32 k] row-major, pad 36.
// Wt:  W chunk transposed [128 n][32 k], pad 36.
// Fragment loads = conflict-free LDS.32 + cvt.rna.tf32.
__global__ __launch_bounds__(256, 2) void k_gemm_tf32(
    const float* __restrict__ X, const float* __restrict__ W,
    float* __restrict__ H, int M)
{
    __shared__ float Asm[128][36];
    __shared__ float Wt[128][36];

    const int tid = threadIdx.x;
    const int lane = tid & 31;
    const int wid = tid >> 5;
    const int warp_m = wid >> 1;
    const int warp_n = wid & 1;
    const int row0 = blockIdx.x * 128;
    const int qr = lane >> 2;      // 0..7
    const int qc = lane & 3;       // 0..3

    float acc[2][8][4];
#pragma unroll
    for (int i = 0; i < 2; i++)
#pragma unroll
        for (int n = 0; n < 8; n++)
#pragma unroll
            for (int q = 0; q < 4; q++) acc[i][n][q] = 0.f;

    for (int k0 = 0; k0 < 128; k0 += 32) {
        // stage A chunk: coalesced float4 both ways
#pragma unroll
        for (int p = 0; p < 4; p++) {
            int idx = tid + p * 256;       // 0..1023
            int r  = idx >> 3;
            int c4 = idx & 7;
            int grow = row0 + r;
            float4 v = make_float4(0.f, 0.f, 0.f, 0.f);
            if (grow < M)
                v = *(const float4*)(X + (size_t)grow * DIM + k0 + c4 * 4);
            *(float4*)&Asm[r][c4 * 4] = v;
        }
        // stage W chunk transposed: 4 coalesced scalar loads -> 1 float4 store
#pragma unroll
        for (int p = 0; p < 4; p++) {
            int idx = tid + p * 256;       // 0..1023
            int n  = idx & 127;
            int kq = (idx >> 7) * 4;       // 0,4,...,28
            float4 t;
            t.x = W[(size_t)(k0 + kq + 0) * DIM + n];
            t.y = W[(size_t)(k0 + kq + 1) * DIM + n];
            t.z = W[(size_t)(k0 + kq + 2) * DIM + n];
            t.w = W[(size_t)(k0 + kq + 3) * DIM + n];
            *(float4*)&Wt[n][kq] = t;
        }
        __syncthreads();

#pragma unroll
        for (int j = 0; j < 4; j++) {
            const int k8 = j * 8;
            uint32_t a[2][4];
#pragma unroll
            for (int i = 0; i < 2; i++) {
                int rb = warp_m * 32 + i * 16 + qr;
                a[i][0] = f2tf32(Asm[rb][k8 + qc]);
                a[i][1] = f2tf32(Asm[rb + 8][k8 + qc]);
                a[i][2] = f2tf32(Asm[rb][k8 + 4 + qc]);
                a[i][3] = f2tf32(Asm[rb + 8][k8 + 4 + qc]);
            }
            uint32_t b[8][2];
#pragma unroll
            for (int n = 0; n < 8; n++) {
                int ng = warp_n * 64 + n * 8 + qr;
                b[n][0] = f2tf32(Wt[ng][k8 + qc]);
                b[n][1] = f2tf32(Wt[ng][k8 + 4 + qc]);
            }
#pragma unroll
            for (int i = 0; i < 2; i++)
#pragma unroll
                for (int n = 0; n < 8; n++) mma_tf32(acc[i][n], a[i], b[n]);
        }
        __syncthreads();
    }

    // epilogue
#pragma unroll
    for (int i = 0; i < 2; i++) {
        int row_lo = row0 + warp_m * 32 + i * 16 + qr;
        int row_hi = row_lo + 8;
#pragma unroll
        for (int n = 0; n < 8; n++) {
            int col = warp_n * 64 + n * 8 + qc * 2;
            if (row_lo < M)
                *(float2*)(H + (size_t)row_lo * DIM + col) =
                    make_float2(acc[i][n][0], acc[i][n][1]);
            if (row_hi < M)
                *(float2*)(H + (size_t)row_hi * DIM + col) =
                    make_float2(acc[i][n][2], acc[i][n][3]);
        }
    }
}

// ---------------------------- gather aggregation ----------------------------
__global__ __launch_bounds__(512) void k_agg(
    const int* __restrict__ rowptr, const int* __restrict__ edst,
    const float* __restrict__ ew, const float* __restrict__ dinv,
    const float* __restrict__ H, const float* __restrict__ bias,
    float* __restrict__ out, int N)
{
    int w = (int)((blockIdx.x * (unsigned)blockDim.x + threadIdx.x) >> 5);
    int lane = threadIdx.x & 31;
    if (w >= N) return;

    int beg = rowptr[w];
    int end = rowptr[w + 1];
    float d = dinv[w];
    float dd = d * d;

    float4 self = *(const float4*)(H + (size_t)w * DIM + lane * 4);
    float4 acc = make_float4(dd * self.x, dd * self.y, dd * self.z, dd * self.w);

#pragma unroll 4
    for (int e = beg; e < end; e++) {
        int r = __ldg(&edst[e]);
        float wgt = __ldg(&ew[e]);
        float4 v = *(const float4*)(H + (size_t)r * DIM + lane * 4);
        acc.x += wgt * v.x;
        acc.y += wgt * v.y;
        acc.z += wgt * v.z;
        acc.w += wgt * v.w;
    }

    float4 bb = *(const float4*)(bias + lane * 4);
    acc.x = fmaxf(acc.x + bb.x, 0.f);
    acc.y = fmaxf(acc.y + bb.y, 0.f);
    acc.z = fmaxf(acc.z + bb.z, 0.f);
    acc.w = fmaxf(acc.w + bb.w, 0.f);
    *(float4*)(out + (size_t)w * DIM + lane * 4) = acc;
}

// ---------------------------- output GEMM (128 -> 40) -----------------------
__global__ __launch_bounds__(256) void k_out_gemm(
    const float* __restrict__ X, const float* __restrict__ Wout,
    const float* __restrict__ bout, float* __restrict__ out, int M)
{
    __shared__ float ws[DIM * 40];
    __shared__ float bs[40];
    __shared__ float xr[8][DIM];

    int tid = threadIdx.x;
    for (int i = tid; i < DIM * 40; i += 256) ws[i] = Wout[i];
    if (tid < 40) bs[tid] = bout[tid];

    int w = tid >> 5, lane = tid & 31;
    int row = blockIdx.x * 8 + w;
    if (row < M)
        *(float4*)&xr[w][lane * 4] = *(const float4*)(X + (size_t)row * DIM + lane * 4);
    __syncthreads();
    if (row >= M) return;

    float acc0 = 0.f, acc1 = 0.f;
    int c1 = lane + 32;
#pragma unroll 8
    for (int k = 0; k < DIM; k++) {
        float xv = xr[w][k];
        acc0 += xv * ws[k * 40 + lane];
        if (c1 < 40) acc1 += xv * ws[k * 40 + c1];
    }
    out[(size_t)row * 40 + lane] = acc0 + bs[lane];
    if (c1 < 40) out[(size_t)row * 40 + c1] = acc1 + bs[c1];
}

// ---------------------------- launcher ---------------------------------------
extern "C" void kernel_launch(void* const* d_in, const int* in_sizes, int n_in,
                              void* d_out, int out_size)
{
    const float* x    = (const float*)d_in[0];
    const int*   ei   = (const int*)d_in[1];
    const float* W1   = (const float*)d_in[2];
    const float* b1   = (const float*)d_in[3];
    const float* W2   = (const float*)d_in[4];
    const float* b2   = (const float*)d_in[5];
    const float* Wout = (const float*)d_in[6];
    const float* bout = (const float*)d_in[7];

    const int N = in_sizes[0] / DIM;
    const int E = in_sizes[1] / 2;
    const int* row = ei;
    const int* col = ei + E;

    void *pa, *pb, *pcnt, *pdinv, *ppart, *pbsum, *prp, *pcur, *pedst, *pew;
    cudaGetSymbolAddress(&pa, g_bufA);
    cudaGetSymbolAddress(&pb, g_bufB);
    cudaGetSymbolAddress(&pcnt, g_cnt);
    cudaGetSymbolAddress(&pdinv, g_dinv);
    cudaGetSymbolAddress(&ppart, g_part);
    cudaGetSymbolAddress(&pbsum, g_bsum);
    cudaGetSymbolAddress(&prp, g_rowptr);
    cudaGetSymbolAddress(&pcur, g_cursor);
    cudaGetSymbolAddress(&pedst, g_edst);
    cudaGetSymbolAddress(&pew, g_ew);

    float* A      = (float*)pa;
    float* B      = (float*)pb;
    int*   cnt    = (int*)pcnt;
    float* dinv   = (float*)pdinv;
    int*   part   = (int*)ppart;
    int*   bsum   = (int*)pbsum;
    int*   rowptr = (int*)prp;
    int*   cursor = (int*)pcur;
    int*   edst   = (int*)pedst;
    float* ew     = (float*)pew;

    const int nb = (N + SCAN_B - 1) / SCAN_B;
    const int gemm_blocks = (N + 127) / 128;
    const int agg_blocks  = (N + 15) / 16;

    // layer-1 GEMM is independent of the CSR build; launch it first
    k_gemm_tf32<<<gemm_blocks, 256>>>(x, W1, A, N);

    // --- CSR build + normalization ---
    cudaMemsetAsync(cnt, 0, (size_t)N * sizeof(int));
    k_count<<<(E + 255) / 256, 256>>>(col, cnt, E);
    k_scan1<<<nb, SCAN_B>>>(cnt, part, bsum, N);
    k_scan2<<<1, 128>>>(bsum, nb);
    k_scan3<<<(N + 255) / 256, 256>>>(part, bsum, rowptr, cursor, N, E);
    k_dinv<<<(N + 255) / 256, 256>>>(cnt, dinv, N);
    k_bucket<<<(E + 255) / 256, 256>>>(row, col, dinv, rowptr, cursor, edst, ew, E);

    // --- layer 1 aggregation ---
    k_agg<<<agg_blocks, 512>>>(rowptr, edst, ew, dinv, A, b1, B, N);

    // --- layer 2 ---
    k_gemm_tf32<<<gemm_blocks, 256>>>(B, W2, A, N);
    k_agg<<<agg_blocks, 512>>>(rowptr, edst, ew, dinv, A, b2, B, N);

    // --- output projection ---
    k_out_gemm<<<(N + 7) / 8, 256>>>(B, Wout, bout, (float*)d_out, N);
}

// round 7
// speedup vs baseline: 1.0050x; 1.0050x over previous
#include <cuda_runtime.h>
#include <cuda_bf16.h>
#include <cstdint>

// ---------------------------------------------------------------------------
// GCN: out = relu(Agg(relu(Agg(x@W1)+b1)@W2)+b2) @ Wout + bout
// Agg(h)[i] = dinv[i]^2*h[i] + sum_{e: col[e]=i} dinv[row]*dinv[col]*h[row]
// CSR build once -> gather agg (fused bias+relu). Hidden GEMMs: tf32
// mma.m16n8k8 with conflict-free row-major staging + cvt at fragment load.
// ---------------------------------------------------------------------------

#define NN 100000
#define EE 1600000
#define DIM 128
#define SCAN_B 1024

__device__ float g_bufA[(size_t)NN * DIM];
__device__ float g_bufB[(size_t)NN * DIM];
__device__ int   g_cnt[NN];
__device__ float g_dinv[NN];
__device__ int   g_part[NN];
__device__ int   g_bsum[128];
__device__ int   g_rowptr[NN + 1];
__device__ int   g_cursor[NN];
__device__ int   g_edst[EE];
__device__ float g_ew[EE];

// ---------------------------- CSR build -------------------------------------
__global__ void k_count(const int* __restrict__ col, int* __restrict__ cnt, int e) {
    int i = blockIdx.x * blockDim.x + threadIdx.x;
    if (i < e) atomicAdd(&cnt[col[i]], 1);
}

__global__ void k_scan1(const int* __restrict__ cnt, int* __restrict__ part,
                        int* __restrict__ bsum, int n) {
    __shared__ int sh[SCAN_B];
    int t = threadIdx.x;
    int g = blockIdx.x * SCAN_B + t;
    int v = (g < n) ? cnt[g] : 0;
    sh[t] = v;
    __syncthreads();
    for (int off = 1; off < SCAN_B; off <<= 1) {
        int x = (t >= off) ? sh[t - off] : 0;
        __syncthreads();
        sh[t] += x;
        __syncthreads();
    }
    if (g < n) part[g] = sh[t] - v;
    if (t == SCAN_B - 1) bsum[blockIdx.x] = sh[t];
}

__global__ void k_scan2(int* bsum, int nb) {
    __shared__ int sh[128];
    int t = threadIdx.x;
    int v = (t < nb) ? bsum[t] : 0;
    sh[t] = v;
    __syncthreads();
    for (int off = 1; off < 128; off <<= 1) {
        int x = (t >= off) ? sh[t - off] : 0;
        __syncthreads();
        sh[t] += x;
        __syncthreads();
    }
    if (t < nb) bsum[t] = sh[t] - v;
}

__global__ void k_scan3(const int* __restrict__ part, const int* __restrict__ bsum,
                        int* __restrict__ rowptr, int* __restrict__ cursor, int n, int e) {
    int g = blockIdx.x * blockDim.x + threadIdx.x;
    if (g < n) {
        rowptr[g] = part[g] + bsum[g / SCAN_B];
        cursor[g] = 0;
    }
    if (g == 0) rowptr[n] = e;
}

__global__ void k_dinv(const int* __restrict__ cnt, float* __restrict__ dinv, int n) {
    int i = blockIdx.x * blockDim.x + threadIdx.x;
    if (i < n) dinv[i] = rsqrtf((float)(cnt[i] + 1));
}

__global__ void k_bucket(const int* __restrict__ row, const int* __restrict__ col,
                         const float* __restrict__ dinv, const int* __restrict__ rowptr,
                         int* __restrict__ cursor, int* __restrict__ edst,
                         float* __restrict__ ew, int E) {
    int e = blockIdx.x * blockDim.x + threadIdx.x;
    if (e >= E) return;
    int c = col[e];
    int r = row[e];
    int p = rowptr[c] + atomicAdd(&cursor[c], 1);
    edst[p] = r;
    ew[p] = dinv[r] * dinv[c];
}

// ---------------------------- tf32 helpers -----------------------------------
__device__ __forceinline__ uint32_t f2tf32(float x) {
    uint32_t u;
    asm("cvt.rna.tf32.f32 %0, %1;" : "=r"(u) : "f"(x));
    return u;
}

__device__ __forceinline__ void mma_tf32(float* c, const uint32_t* a, const uint32_t* b) {
    asm volatile(
        "mma.sync.aligned.m16n8k8.row.col.f32.tf32.tf32.f32 "
        "{%0,%1,%2,%3}, {%4,%5,%6,%7}, {%8,%9}, {%0,%1,%2,%3};"
        : "+f"(c[0]), "+f"(c[1]), "+f"(c[2]), "+f"(c[3])
        : "r"(a[0]), "r"(a[1]), "r"(a[2]), "r"(a[3]), "r"(b[0]), "r"(b[1]));
}

// ---------------------------- tf32 GEMM (N=K=128) ----------------------------
// 128x128 tile, 256 threads, 8 warps (4m x 2n), each warp 32x64.
// Asm: X chunk [128 rows][32 k] row-major, pad 36.
// Wt:  W chunk transposed [128 n][32 k], pad 36.
// Fragment loads = conflict-free LDS.32 + cvt.rna.tf32.
__global__ __launch_bounds__(256, 2) void k_gemm_tf32(
    const float* __restrict__ X, const float* __restrict__ W,
    float* __restrict__ H, int M)
{
    __shared__ float Asm[128][36];
    __shared__ float Wt[128][36];

    const int tid = threadIdx.x;
    const int lane = tid & 31;
    const int wid = tid >> 5;
    const int warp_m = wid >> 1;
    const int warp_n = wid & 1;
    const int row0 = blockIdx.x * 128;
    const int qr = lane >> 2;      // 0..7
    const int qc = lane & 3;       // 0..3

    float acc[2][8][4];
#pragma unroll
    for (int i = 0; i < 2; i++)
#pragma unroll
        for (int n = 0; n < 8; n++)
#pragma unroll
            for (int q = 0; q < 4; q++) acc[i][n][q] = 0.f;

    for (int k0 = 0; k0 < 128; k0 += 32) {
        // stage A chunk: coalesced float4 both ways
#pragma unroll
        for (int p = 0; p < 4; p++) {
            int idx = tid + p * 256;       // 0..1023
            int r  = idx >> 3;
            int c4 = idx & 7;
            int grow = row0 + r;
            float4 v = make_float4(0.f, 0.f, 0.f, 0.f);
            if (grow < M)
                v = *(const float4*)(X + (size_t)grow * DIM + k0 + c4 * 4);
            *(float4*)&Asm[r][c4 * 4] = v;
        }
        // stage W chunk transposed: 4 coalesced scalar loads -> 1 float4 store
#pragma unroll
        for (int p = 0; p < 4; p++) {
            int idx = tid + p * 256;       // 0..1023
            int n  = idx & 127;
            int kq = (idx >> 7) * 4;       // 0,4,...,28
            float4 t;
            t.x = W[(size_t)(k0 + kq + 0) * DIM + n];
            t.y = W[(size_t)(k0 + kq + 1) * DIM + n];
            t.z = W[(size_t)(k0 + kq + 2) * DIM + n];
            t.w = W[(size_t)(k0 + kq + 3) * DIM + n];
            *(float4*)&Wt[n][kq] = t;
        }
        __syncthreads();

#pragma unroll
        for (int j = 0; j < 4; j++) {
            const int k8 = j * 8;
            uint32_t a[2][4];
#pragma unroll
            for (int i = 0; i < 2; i++) {
                int rb = warp_m * 32 + i * 16 + qr;
                a[i][0] = f2tf32(Asm[rb][k8 + qc]);
                a[i][1] = f2tf32(Asm[rb + 8][k8 + qc]);
                a[i][2] = f2tf32(Asm[rb][k8 + 4 + qc]);
                a[i][3] = f2tf32(Asm[rb + 8][k8 + 4 + qc]);
            }
            uint32_t b[8][2];
#pragma unroll
            for (int n = 0; n < 8; n++) {
                int ng = warp_n * 64 + n * 8 + qr;
                b[n][0] = f2tf32(Wt[ng][k8 + qc]);
                b[n][1] = f2tf32(Wt[ng][k8 + 4 + qc]);
            }
#pragma unroll
            for (int i = 0; i < 2; i++)
#pragma unroll
                for (int n = 0; n < 8; n++) mma_tf32(acc[i][n], a[i], b[n]);
        }
        __syncthreads();
    }

    // epilogue
#pragma unroll
    for (int i = 0; i < 2; i++) {
        int row_lo = row0 + warp_m * 32 + i * 16 + qr;
        int row_hi = row_lo + 8;
#pragma unroll
        for (int n = 0; n < 8; n++) {
            int col = warp_n * 64 + n * 8 + qc * 2;
            if (row_lo < M)
                *(float2*)(H + (size_t)row_lo * DIM + col) =
                    make_float2(acc[i][n][0], acc[i][n][1]);
            if (row_hi < M)
                *(float2*)(H + (size_t)row_hi * DIM + col) =
                    make_float2(acc[i][n][2], acc[i][n][3]);
        }
    }
}

// ---------------------------- gather aggregation ----------------------------
__global__ __launch_bounds__(512) void k_agg(
    const int* __restrict__ rowptr, const int* __restrict__ edst,
    const float* __restrict__ ew, const float* __restrict__ dinv,
    const float* __restrict__ H, const float* __restrict__ bias,
    float* __restrict__ out, int N)
{
    int w = (int)((blockIdx.x * (unsigned)blockDim.x + threadIdx.x) >> 5);
    int lane = threadIdx.x & 31;
    if (w >= N) return;

    int beg = rowptr[w];
    int end = rowptr[w + 1];
    float d = dinv[w];
    float dd = d * d;

    float4 self = *(const float4*)(H + (size_t)w * DIM + lane * 4);
    float4 acc = make_float4(dd * self.x, dd * self.y, dd * self.z, dd * self.w);

#pragma unroll 4
    for (int e = beg; e < end; e++) {
        int r = __ldg(&edst[e]);
        float wgt = __ldg(&ew[e]);
        float4 v = *(const float4*)(H + (size_t)r * DIM + lane * 4);
        acc.x += wgt * v.x;
        acc.y += wgt * v.y;
        acc.z += wgt * v.z;
        acc.w += wgt * v.w;
    }

    float4 bb = *(const float4*)(bias + lane * 4);
    acc.x = fmaxf(acc.x + bb.x, 0.f);
    acc.y = fmaxf(acc.y + bb.y, 0.f);
    acc.z = fmaxf(acc.z + bb.z, 0.f);
    acc.w = fmaxf(acc.w + bb.w, 0.f);
    *(float4*)(out + (size_t)w * DIM + lane * 4) = acc;
}

// ---------------------------- output GEMM (128 -> 40) -----------------------
__global__ __launch_bounds__(256) void k_out_gemm(
    const float* __restrict__ X, const float* __restrict__ Wout,
    const float* __restrict__ bout, float* __restrict__ out, int M)
{
    __shared__ float ws[DIM * 40];
    __shared__ float bs[40];
    __shared__ float xr[8][DIM];

    int tid = threadIdx.x;
    for (int i = tid; i < DIM * 40; i += 256) ws[i] = Wout[i];
    if (tid < 40) bs[tid] = bout[tid];

    int w = tid >> 5, lane = tid & 31;
    int row = blockIdx.x * 8 + w;
    if (row < M)
        *(float4*)&xr[w][lane * 4] = *(const float4*)(X + (size_t)row * DIM + lane * 4);
    __syncthreads();
    if (row >= M) return;

    float acc0 = 0.f, acc1 = 0.f;
    int c1 = lane + 32;
#pragma unroll 8
    for (int k = 0; k < DIM; k++) {
        float xv = xr[w][k];
        acc0 += xv * ws[k * 40 + lane];
        if (c1 < 40) acc1 += xv * ws[k * 40 + c1];
    }
    out[(size_t)row * 40 + lane] = acc0 + bs[lane];
    if (c1 < 40) out[(size_t)row * 40 + c1] = acc1 + bs[c1];
}

// ---------------------------- launcher ---------------------------------------
extern "C" void kernel_launch(void* const* d_in, const int* in_sizes, int n_in,
                              void* d_out, int out_size)
{
    const float* x    = (const float*)d_in[0];
    const int*   ei   = (const int*)d_in[1];
    const float* W1   = (const float*)d_in[2];
    const float* b1   = (const float*)d_in[3];
    const float* W2   = (const float*)d_in[4];
    const float* b2   = (const float*)d_in[5];
    const float* Wout = (const float*)d_in[6];
    const float* bout = (const float*)d_in[7];

    const int N = in_sizes[0] / DIM;
    const int E = in_sizes[1] / 2;
    const int* row = ei;
    const int* col = ei + E;

    void *pa, *pb, *pcnt, *pdinv, *ppart, *pbsum, *prp, *pcur, *pedst, *pew;
    cudaGetSymbolAddress(&pa, g_bufA);
    cudaGetSymbolAddress(&pb, g_bufB);
    cudaGetSymbolAddress(&pcnt, g_cnt);
    cudaGetSymbolAddress(&pdinv, g_dinv);
    cudaGetSymbolAddress(&ppart, g_part);
    cudaGetSymbolAddress(&pbsum, g_bsum);
    cudaGetSymbolAddress(&prp, g_rowptr);
    cudaGetSymbolAddress(&pcur, g_cursor);
    cudaGetSymbolAddress(&pedst, g_edst);
    cudaGetSymbolAddress(&pew, g_ew);

    float* A      = (float*)pa;
    float* B      = (float*)pb;
    int*   cnt    = (int*)pcnt;
    float* dinv   = (float*)pdinv;
    int*   part   = (int*)ppart;
    int*   bsum   = (int*)pbsum;
    int*   rowptr = (int*)prp;
    int*   cursor = (int*)pcur;
    int*   edst   = (int*)pedst;
    float* ew     = (float*)pew;

    const int nb = (N + SCAN_B - 1) / SCAN_B;
    const int gemm_blocks = (N + 127) / 128;
    const int agg_blocks  = (N + 15) / 16;

    // layer-1 GEMM is independent of the CSR build; launch it first
    k_gemm_tf32<<<gemm_blocks, 256>>>(x, W1, A, N);

    // --- CSR build + normalization ---
    cudaMemsetAsync(cnt, 0, (size_t)N * sizeof(int));
    k_count<<<(E + 255) / 256, 256>>>(col, cnt, E);
    k_scan1<<<nb, SCAN_B>>>(cnt, part, bsum, N);
    k_scan2<<<1, 128>>>(bsum, nb);
    k_scan3<<<(N + 255) / 256, 256>>>(part, bsum, rowptr, cursor, N, E);
    k_dinv<<<(N + 255) / 256, 256>>>(cnt, dinv, N);
    k_bucket<<<(E + 255) / 256, 256>>>(row, col, dinv, rowptr, cursor, edst, ew, E);

    // --- layer 1 aggregation ---
    k_agg<<<agg_blocks, 512>>>(rowptr, edst, ew, dinv, A, b1, B, N);

    // --- layer 2 ---
    k_gemm_tf32<<<gemm_blocks, 256>>>(B, W2, A, N);
    k_agg<<<agg_blocks, 512>>>(rowptr, edst, ew, dinv, A, b2, B, N);

    // --- output projection ---
    k_out_gemm<<<(N + 7) / 8, 256>>>(B, Wout, bout, (float*)d_out, N);
}